// round 7
// baseline (speedup 1.0000x reference)
#include <cuda_runtime.h>
#include <cstdint>
#include <cstddef>

// Problem constants
#define NTOK   2048          // B*S
#define DMODEL 2048
#define DFF    8192
#define NEXP   4
#define TOPK   2
#define CAP    2048          // worst-case tokens per expert

// ---------------------------------------------------------------------------
// Scratch (static device globals; no allocation anywhere)
// ---------------------------------------------------------------------------
__device__ int   g_cnt[NEXP];
__device__ int   g_list[NEXP * CAP];       // token index per (expert, slot)
__device__ int   g_tok_e[NTOK * TOPK];     // chosen expert per (token, k)
__device__ int   g_tok_r[NTOK * TOPK];     // slot within expert list
__device__ float g_tok_v[NTOK * TOPK];     // gate value (softmax prob)
__device__ __align__(256) float g_H[(size_t)NEXP * CAP * DFF];     // 268 MB
__device__ __align__(256) float g_O[(size_t)NEXP * CAP * DMODEL];  //  67 MB

// ---------------------------------------------------------------------------
// TF32 helpers
// ---------------------------------------------------------------------------
__device__ __forceinline__ unsigned f2tf(float x) {
    unsigned u;
    asm("cvt.rna.tf32.f32 %0, %1;" : "=r"(u) : "f"(x));
    return u;
}

__device__ __forceinline__ void mma_tf32(float* c, const unsigned* a, const unsigned* b) {
    asm volatile(
        "mma.sync.aligned.m16n8k8.row.col.f32.tf32.tf32.f32 "
        "{%0,%1,%2,%3}, {%4,%5,%6,%7}, {%8,%9}, {%0,%1,%2,%3};"
        : "+f"(c[0]), "+f"(c[1]), "+f"(c[2]), "+f"(c[3])
        : "r"(a[0]), "r"(a[1]), "r"(a[2]), "r"(a[3]), "r"(b[0]), "r"(b[1]));
}

// ---------------------------------------------------------------------------
// Kernel 0: reset per-expert counters (runs every graph replay)
// ---------------------------------------------------------------------------
__global__ void init_kernel() {
    if (threadIdx.x < NEXP) g_cnt[threadIdx.x] = 0;
}

// ---------------------------------------------------------------------------
// Kernel 1: router.  One 128-thread block per token.
// logits = x[t] @ Wr ; softmax ; top-2 ; assign slots.
// ---------------------------------------------------------------------------
__global__ void router_kernel(const float* __restrict__ x, const float* __restrict__ Wr) {
    const int t = blockIdx.x;
    const float* xr = x + (size_t)t * DMODEL;

    float a0 = 0.f, a1 = 0.f, a2 = 0.f, a3 = 0.f;
    for (int d = threadIdx.x; d < DMODEL; d += 128) {
        float xv = xr[d];
        const float* w = Wr + d * NEXP;
        a0 += xv * w[0]; a1 += xv * w[1]; a2 += xv * w[2]; a3 += xv * w[3];
    }
    #pragma unroll
    for (int o = 16; o > 0; o >>= 1) {
        a0 += __shfl_xor_sync(0xffffffffu, a0, o);
        a1 += __shfl_xor_sync(0xffffffffu, a1, o);
        a2 += __shfl_xor_sync(0xffffffffu, a2, o);
        a3 += __shfl_xor_sync(0xffffffffu, a3, o);
    }
    __shared__ float red[4][NEXP];
    const int warp = threadIdx.x >> 5;
    if ((threadIdx.x & 31) == 0) {
        red[warp][0] = a0; red[warp][1] = a1; red[warp][2] = a2; red[warp][3] = a3;
    }
    __syncthreads();
    if (threadIdx.x == 0) {
        float l[NEXP];
        #pragma unroll
        for (int e = 0; e < NEXP; e++)
            l[e] = red[0][e] + red[1][e] + red[2][e] + red[3][e];
        float mx = l[0];
        #pragma unroll
        for (int e = 1; e < NEXP; e++) mx = fmaxf(mx, l[e]);
        float p[NEXP]; float s = 0.f;
        #pragma unroll
        for (int e = 0; e < NEXP; e++) { p[e] = __expf(l[e] - mx); s += p[e]; }
        float inv = 1.f / s;
        #pragma unroll
        for (int e = 0; e < NEXP; e++) p[e] *= inv;
        // top-2 (ties -> lowest index first, matching lax.top_k)
        int e0 = 0;
        #pragma unroll
        for (int e = 1; e < NEXP; e++) if (p[e] > p[e0]) e0 = e;
        int e1 = (e0 == 0) ? 1 : 0;
        #pragma unroll
        for (int e = 0; e < NEXP; e++) if (e != e0 && p[e] > p[e1]) e1 = e;

        int s0 = atomicAdd(&g_cnt[e0], 1);
        g_list[e0 * CAP + s0] = t;
        g_tok_e[2*t + 0] = e0; g_tok_r[2*t + 0] = s0; g_tok_v[2*t + 0] = p[e0];

        int s1 = atomicAdd(&g_cnt[e1], 1);
        g_list[e1 * CAP + s1] = t;
        g_tok_e[2*t + 1] = e1; g_tok_r[2*t + 1] = s1; g_tok_v[2*t + 1] = p[e1];
    }
}

// ---------------------------------------------------------------------------
// Kernel 2: fused dual GEMM per expert.
//   g = gather(X) @ Wg[e], u = gather(X) @ Wu[e]; H = silu(g) * u
// Tile 128(M) x 64(N) x 16(K). 8 warps: 4 in M x 2 in N; warp tile 32x32.
// ---------------------------------------------------------------------------
__global__ __launch_bounds__(256, 1) void gemm1_kernel(
    const float* __restrict__ x,
    const float* __restrict__ Wg,
    const float* __restrict__ Wu)
{
    const int e   = blockIdx.z;
    const int mt  = blockIdx.y;
    const int nt  = blockIdx.x;
    const int cnt = g_cnt[e];
    if (mt * 128 >= cnt) return;

    __shared__ float As[16][132];   // k-major, padded (conflict-free frag loads)
    __shared__ float BsG[16][68];
    __shared__ float BsU[16][68];

    const int tid  = threadIdx.x;
    const int lane = tid & 31;
    const int warp = tid >> 5;
    const int gid  = lane >> 2;
    const int tig  = lane & 3;
    const int wmb  = (warp & 3) * 32;   // warp M base
    const int wnb  = (warp >> 2) * 32;  // warp N base

    // ---- global load mapping ----
    const int am  = tid >> 2;           // 0..63 (rows am, am+64)
    const int akc = (tid & 3) * 4;      // k offset within tile
    const int mg0 = mt * 128 + am;
    const int mg1 = mg0 + 64;
    const float* asrc0 = (mg0 < cnt) ? (x + (size_t)g_list[e*CAP + mg0] * DMODEL + akc) : nullptr;
    const float* asrc1 = (mg1 < cnt) ? (x + (size_t)g_list[e*CAP + mg1] * DMODEL + akc) : nullptr;

    const int bk = tid >> 4;            // 0..15
    const int bn = (tid & 15) * 4;      // 0..60
    const float* bgsrc = Wg + (size_t)e*DMODEL*DFF + (size_t)bk*DFF + (size_t)nt*64 + bn;
    const float* busrc = Wu + (size_t)e*DMODEL*DFF + (size_t)bk*DFF + (size_t)nt*64 + bn;

    float4 ra0, ra1, rbg, rbu;
    float cg[2][4][4], cu[2][4][4];
    #pragma unroll
    for (int i = 0; i < 2; i++)
        #pragma unroll
        for (int j = 0; j < 4; j++)
            #pragma unroll
            for (int r = 0; r < 4; r++) { cg[i][j][r] = 0.f; cu[i][j][r] = 0.f; }

#define G1_LOAD(kt) do {                                                              \
        ra0 = asrc0 ? *(const float4*)(asrc0 + (size_t)(kt)*16) : make_float4(0,0,0,0);\
        ra1 = asrc1 ? *(const float4*)(asrc1 + (size_t)(kt)*16) : make_float4(0,0,0,0);\
        rbg = *(const float4*)(bgsrc + (size_t)(kt)*16*DFF);                           \
        rbu = *(const float4*)(busrc + (size_t)(kt)*16*DFF);                           \
    } while (0)
#define G1_STORE() do {                                                               \
        As[akc+0][am]    = ra0.x; As[akc+1][am]    = ra0.y;                            \
        As[akc+2][am]    = ra0.z; As[akc+3][am]    = ra0.w;                            \
        As[akc+0][am+64] = ra1.x; As[akc+1][am+64] = ra1.y;                            \
        As[akc+2][am+64] = ra1.z; As[akc+3][am+64] = ra1.w;                            \
        *(float4*)&BsG[bk][bn] = rbg;                                                  \
        *(float4*)&BsU[bk][bn] = rbu;                                                  \
    } while (0)

    G1_LOAD(0);
    G1_STORE();
    __syncthreads();

    const int NKT = DMODEL / 16;
    for (int kt = 0; kt < NKT; kt++) {
        if (kt + 1 < NKT) G1_LOAD(kt + 1);
        #pragma unroll
        for (int kk = 0; kk < 16; kk += 8) {
            unsigned a[2][4], bG[4][2], bU[4][2];
            #pragma unroll
            for (int mf = 0; mf < 2; mf++) {
                int mr = wmb + mf*16 + gid;
                a[mf][0] = f2tf(As[kk+tig  ][mr]);
                a[mf][1] = f2tf(As[kk+tig  ][mr+8]);
                a[mf][2] = f2tf(As[kk+tig+4][mr]);
                a[mf][3] = f2tf(As[kk+tig+4][mr+8]);
            }
            #pragma unroll
            for (int nf = 0; nf < 4; nf++) {
                int nc = wnb + nf*8 + gid;
                bG[nf][0] = f2tf(BsG[kk+tig  ][nc]);
                bG[nf][1] = f2tf(BsG[kk+tig+4][nc]);
                bU[nf][0] = f2tf(BsU[kk+tig  ][nc]);
                bU[nf][1] = f2tf(BsU[kk+tig+4][nc]);
            }
            #pragma unroll
            for (int mf = 0; mf < 2; mf++)
                #pragma unroll
                for (int nf = 0; nf < 4; nf++) {
                    mma_tf32(cg[mf][nf], a[mf], bG[nf]);
                    mma_tf32(cu[mf][nf], a[mf], bU[nf]);
                }
        }
        __syncthreads();
        if (kt + 1 < NKT) { G1_STORE(); __syncthreads(); }
    }

    // epilogue: H = silu(g) * u  (padded rows produce exactly 0)
    float* Hbase = g_H + ((size_t)e*CAP + (size_t)mt*128) * DFF + (size_t)nt*64;
    #pragma unroll
    for (int mf = 0; mf < 2; mf++) {
        #pragma unroll
        for (int nf = 0; nf < 4; nf++) {
            int r0 = wmb + mf*16 + gid;
            int c0 = wnb + nf*8 + tig*2;
            float* p0 = Hbase + (size_t)r0 * DFF + c0;
            float* p1 = Hbase + (size_t)(r0 + 8) * DFF + c0;
            float g0 = cg[mf][nf][0], g1 = cg[mf][nf][1];
            float g2 = cg[mf][nf][2], g3 = cg[mf][nf][3];
            p0[0] = (g0 / (1.f + __expf(-g0))) * cu[mf][nf][0];
            p0[1] = (g1 / (1.f + __expf(-g1))) * cu[mf][nf][1];
            p1[0] = (g2 / (1.f + __expf(-g2))) * cu[mf][nf][2];
            p1[1] = (g3 / (1.f + __expf(-g3))) * cu[mf][nf][3];
        }
    }
#undef G1_LOAD
#undef G1_STORE
}

// ---------------------------------------------------------------------------
// Kernel 3: O = H @ Wd[e].  Tile 128 x 128 x 16. 8 warps: 2(M) x 4(N),
// warp tile 64 x 32.
// ---------------------------------------------------------------------------
__global__ __launch_bounds__(256, 1) void gemm2_kernel(const float* __restrict__ Wd)
{
    const int e   = blockIdx.z;
    const int mt  = blockIdx.y;
    const int nt  = blockIdx.x;
    const int cnt = g_cnt[e];
    if (mt * 128 >= cnt) return;

    __shared__ float As[16][132];
    __shared__ float Bs[16][132];

    const int tid  = threadIdx.x;
    const int lane = tid & 31;
    const int warp = tid >> 5;
    const int gid  = lane >> 2;
    const int tig  = lane & 3;
    const int wmb  = (warp & 1) * 64;
    const int wnb  = (warp >> 1) * 32;

    const int am  = tid >> 2;
    const int akc = (tid & 3) * 4;
    const float* asrc0 = g_H + ((size_t)e*CAP + (size_t)mt*128 + am) * DFF + akc;
    const float* asrc1 = asrc0 + (size_t)64 * DFF;

    const int bk = tid >> 5;            // 0..7 (rows bk, bk+8)
    const int bn = (tid & 31) * 4;      // 0..124
    const float* bsrc0 = Wd + (size_t)e*DFF*DMODEL + (size_t)bk*DMODEL + (size_t)nt*128 + bn;
    const float* bsrc1 = bsrc0 + (size_t)8 * DMODEL;

    float4 ra0, ra1, rb0, rb1;
    float c[4][4][4];
    #pragma unroll
    for (int i = 0; i < 4; i++)
        #pragma unroll
        for (int j = 0; j < 4; j++)
            #pragma unroll
            for (int r = 0; r < 4; r++) c[i][j][r] = 0.f;

#define G2_LOAD(kt) do {                                                     \
        ra0 = *(const float4*)(asrc0 + (size_t)(kt)*16);                      \
        ra1 = *(const float4*)(asrc1 + (size_t)(kt)*16);                      \
        rb0 = *(const float4*)(bsrc0 + (size_t)(kt)*16*DMODEL);               \
        rb1 = *(const float4*)(bsrc1 + (size_t)(kt)*16*DMODEL);               \
    } while (0)
#define G2_STORE() do {                                                      \
        As[akc+0][am]    = ra0.x; As[akc+1][am]    = ra0.y;                   \
        As[akc+2][am]    = ra0.z; As[akc+3][am]    = ra0.w;                   \
        As[akc+0][am+64] = ra1.x; As[akc+1][am+64] = ra1.y;                   \
        As[akc+2][am+64] = ra1.z; As[akc+3][am+64] = ra1.w;                   \
        *(float4*)&Bs[bk][bn]   = rb0;                                        \
        *(float4*)&Bs[bk+8][bn] = rb1;                                        \
    } while (0)

    G2_LOAD(0);
    G2_STORE();
    __syncthreads();

    const int NKT = DFF / 16;
    for (int kt = 0; kt < NKT; kt++) {
        if (kt + 1 < NKT) G2_LOAD(kt + 1);
        #pragma unroll
        for (int kk = 0; kk < 16; kk += 8) {
            unsigned a[4][4], b[4][2];
            #pragma unroll
            for (int mf = 0; mf < 4; mf++) {
                int mr = wmb + mf*16 + gid;
                a[mf][0] = f2tf(As[kk+tig  ][mr]);
                a[mf][1] = f2tf(As[kk+tig  ][mr+8]);
                a[mf][2] = f2tf(As[kk+tig+4][mr]);
                a[mf][3] = f2tf(As[kk+tig+4][mr+8]);
            }
            #pragma unroll
            for (int nf = 0; nf < 4; nf++) {
                int nc = wnb + nf*8 + gid;
                b[nf][0] = f2tf(Bs[kk+tig  ][nc]);
                b[nf][1] = f2tf(Bs[kk+tig+4][nc]);
            }
            #pragma unroll
            for (int mf = 0; mf < 4; mf++)
                #pragma unroll
                for (int nf = 0; nf < 4; nf++)
                    mma_tf32(c[mf][nf], a[mf], b[nf]);
        }
        __syncthreads();
        if (kt + 1 < NKT) { G2_STORE(); __syncthreads(); }
    }

    float* Obase = g_O + ((size_t)e*CAP + (size_t)mt*128) * DMODEL + (size_t)nt*128;
    #pragma unroll
    for (int mf = 0; mf < 4; mf++) {
        #pragma unroll
        for (int nf = 0; nf < 4; nf++) {
            int r0 = wmb + mf*16 + gid;
            int c0 = wnb + nf*8 + tig*2;
            float* p0 = Obase + (size_t)r0 * DMODEL + c0;
            float* p1 = Obase + (size_t)(r0 + 8) * DMODEL + c0;
            p0[0] = c[mf][nf][0]; p0[1] = c[mf][nf][1];
            p1[0] = c[mf][nf][2]; p1[1] = c[mf][nf][3];
        }
    }
#undef G2_LOAD
#undef G2_STORE
}

// ---------------------------------------------------------------------------
// Kernel 4: combine.  out[t] = v0*O[e0][r0] + v1*O[e1][r1]
// ---------------------------------------------------------------------------
__global__ void combine_kernel(float* __restrict__ out) {
    const int t  = blockIdx.x;
    const int e0 = g_tok_e[2*t + 0], e1 = g_tok_e[2*t + 1];
    const int r0 = g_tok_r[2*t + 0], r1 = g_tok_r[2*t + 1];
    const float v0 = g_tok_v[2*t + 0], v1 = g_tok_v[2*t + 1];
    const float4* o0 = (const float4*)(g_O + ((size_t)e0*CAP + r0) * DMODEL);
    const float4* o1 = (const float4*)(g_O + ((size_t)e1*CAP + r1) * DMODEL);
    float4* dst = (float4*)(out + (size_t)t * DMODEL);
    for (int i = threadIdx.x; i < DMODEL / 4; i += blockDim.x) {
        float4 a = o0[i], b = o1[i];
        float4 r;
        r.x = v0 * a.x + v1 * b.x;
        r.y = v0 * a.y + v1 * b.y;
        r.z = v0 * a.z + v1 * b.z;
        r.w = v0 * a.w + v1 * b.w;
        dst[i] = r;
    }
}

// ---------------------------------------------------------------------------
// Launch
// ---------------------------------------------------------------------------
extern "C" void kernel_launch(void* const* d_in, const int* in_sizes, int n_in,
                              void* d_out, int out_size) {
    const float* x  = (const float*)d_in[0];   // [B,S,D]
    const float* Wr = (const float*)d_in[1];   // [D,E]
    const float* Wg = (const float*)d_in[2];   // [E,D,F]
    const float* Wu = (const float*)d_in[3];   // [E,D,F]
    const float* Wd = (const float*)d_in[4];   // [E,F,D]
    float* out = (float*)d_out;                // [B,S,D]

    init_kernel<<<1, 32>>>();
    router_kernel<<<NTOK, 128>>>(x, Wr);

    dim3 grid1(DFF / 64, CAP / 128, NEXP);     // (128, 16, 4)
    gemm1_kernel<<<grid1, 256>>>(x, Wg, Wu);

    dim3 grid2(DMODEL / 128, CAP / 128, NEXP); // (16, 16, 4)
    gemm2_kernel<<<grid2, 256>>>(Wd);

    combine_kernel<<<NTOK, 256>>>(out);
}